// round 1
// baseline (speedup 1.0000x reference)
#include <cuda_runtime.h>

// Shapes (fixed by the problem; derived at launch from in_sizes for safety)
#define D    256
#define DC   32      // d-chunk depth
#define TM   128     // token tile
#define TN   128     // code tile
#define MAXK 2048
#define MAXN 65536

#define COMMIT_COST 0.25f
#define DIV_GAMMA   0.1f
#define EPS_F       1e-8f

// ---------------- device scratch (no allocations allowed) ----------------
__device__ float g_esq[MAXK];
__device__ float g_rn[MAXK];
__device__ float g_rninv[MAXK];
__device__ float g_xsq[MAXN];
__device__ int   g_idx[MAXN];
__device__ float g_counts[MAXK];
__device__ float g_acc[4];   // 0: mse_sum, 1: abs-offdiag sum, 2: rownorm sum

// ---------------- f32x2 packed-FMA helpers (sm_100+ PTX) ----------------
__device__ __forceinline__ unsigned long long pk2(float lo, float hi) {
    unsigned long long r;
    asm("mov.b64 %0, {%1,%2};" : "=l"(r) : "r"(__float_as_uint(lo)), "r"(__float_as_uint(hi)));
    return r;
}
__device__ __forceinline__ void fma2(unsigned long long& c, unsigned long long a, unsigned long long b) {
    asm("fma.rn.f32x2 %0, %1, %2, %0;" : "+l"(c) : "l"(a), "l"(b));
}
__device__ __forceinline__ float2 up2(unsigned long long v) {
    unsigned int lo, hi;
    asm("mov.b64 {%0,%1}, %2;" : "=r"(lo), "=r"(hi) : "l"(v));
    return make_float2(__uint_as_float(lo), __uint_as_float(hi));
}

// ---------------- shared-tile loader: [128 rows][32 d], XOR-swizzled ----------------
// Tile stored as float4 granules: S4[row*8 + (g ^ ((row>>2)&7))]
__device__ __forceinline__ void load_tile(float4* S4, const float* __restrict__ g, int tid) {
    int r  = tid >> 3;   // 0..31
    int gq = tid & 7;    // granule 0..7
#pragma unroll
    for (int p = 0; p < 4; p++) {
        int row = p * 32 + r;
        float4 v = *reinterpret_cast<const float4*>(g + (size_t)row * D + gq * 4);
        S4[row * 8 + (gq ^ ((row >> 2) & 7))] = v;
    }
}

// ---------------- 128x128x32 micro-GEMM step, acc in f32x2 pairs ----------------
// acc[mi][p]: mi -> token rows {4*ty+0..3, 64+4*ty+0..3}
//             p  -> code pairs (4tx,4tx+1),(4tx+2,4tx+3),(64+4tx,..+1),(..+2,..+3)
__device__ __forceinline__ void chunk_mma(const float4* __restrict__ Xs4,
                                          const float4* __restrict__ Es4,
                                          int ty, int tx,
                                          unsigned long long acc[8][4]) {
    int cb = tx & 7;  // b-side swizzle constant (same for all this thread's n-rows)
    int ca = ty & 7;  // a-side swizzle constant
#pragma unroll
    for (int s = 0; s < 8; s++) {       // 4 d-values per step
        int gb = s ^ cb;
        int ga = s ^ ca;
        unsigned long long b2[4][4];
#pragma unroll
        for (int p = 0; p < 4; p++) {
            int nA = (p < 2) ? (4 * tx + 2 * p) : (64 + 4 * tx + 2 * (p - 2));
            float4 u = Es4[nA * 8 + gb];
            float4 w = Es4[(nA + 1) * 8 + gb];
            b2[p][0] = pk2(u.x, w.x);
            b2[p][1] = pk2(u.y, w.y);
            b2[p][2] = pk2(u.z, w.z);
            b2[p][3] = pk2(u.w, w.w);
        }
#pragma unroll
        for (int mi = 0; mi < 8; mi++) {
            int m = (mi < 4) ? (4 * ty + mi) : (64 + 4 * ty + (mi - 4));
            float4 a4 = Xs4[m * 8 + ga];
            float af[4] = {a4.x, a4.y, a4.z, a4.w};
#pragma unroll
            for (int jd = 0; jd < 4; jd++) {
                unsigned long long a2 = pk2(af[jd], af[jd]);
                fma2(acc[mi][0], a2, b2[0][jd]);
                fma2(acc[mi][1], a2, b2[1][jd]);
                fma2(acc[mi][2], a2, b2[2][jd]);
                fma2(acc[mi][3], a2, b2[3][jd]);
            }
        }
    }
}

// ---------------- k_init: zero accumulators ----------------
__global__ void k_init(int K) {
    int i = blockIdx.x * blockDim.x + threadIdx.x;
    if (i < K) g_counts[i] = 0.f;
    if (i < 4) g_acc[i] = 0.f;
}

// ---------------- k_prep: esq, rownorm, 1/rownorm, sum(rownorm) ----------------
__global__ void k_prep(const float* __restrict__ e, int K) {
    int w    = (blockIdx.x * blockDim.x + threadIdx.x) >> 5;  // one warp per row
    int lane = threadIdx.x & 31;
    if (w >= K) return;
    const float4* er = reinterpret_cast<const float4*>(e + (size_t)w * D);
    float4 a = er[lane], b = er[32 + lane];
    float s = __fadd_rn(
        __fadd_rn(__fadd_rn(__fmul_rn(a.x,a.x), __fmul_rn(a.y,a.y)),
                  __fadd_rn(__fmul_rn(a.z,a.z), __fmul_rn(a.w,a.w))),
        __fadd_rn(__fadd_rn(__fmul_rn(b.x,b.x), __fmul_rn(b.y,b.y)),
                  __fadd_rn(__fmul_rn(b.z,b.z), __fmul_rn(b.w,b.w))));
#pragma unroll
    for (int off = 16; off > 0; off >>= 1) s += __shfl_xor_sync(0xffffffffu, s, off);
    if (lane == 0) {
        g_esq[w] = s;
        float rn = sqrtf(s);
        g_rn[w] = rn;
        g_rninv[w] = 1.0f / fmaxf(rn, 1e-12f);
        atomicAdd(&g_acc[2], rn);
    }
}

// ---------------- k_xsq: per-token ||x||^2 (pairwise-ish, no FMA contraction) ----------------
__global__ void k_xsq(const float* __restrict__ x, int N) {
    int w    = (blockIdx.x * blockDim.x + threadIdx.x) >> 5;
    int lane = threadIdx.x & 31;
    if (w >= N) return;
    const float4* xr = reinterpret_cast<const float4*>(x + (size_t)w * D);
    float4 a = xr[lane], b = xr[32 + lane];
    float s = __fadd_rn(
        __fadd_rn(__fadd_rn(__fmul_rn(a.x,a.x), __fmul_rn(a.y,a.y)),
                  __fadd_rn(__fmul_rn(a.z,a.z), __fmul_rn(a.w,a.w))),
        __fadd_rn(__fadd_rn(__fmul_rn(b.x,b.x), __fmul_rn(b.y,b.y)),
                  __fadd_rn(__fmul_rn(b.z,b.z), __fmul_rn(b.w,b.w))));
#pragma unroll
    for (int off = 16; off > 0; off >>= 1) s += __shfl_xor_sync(0xffffffffu, s, off);
    if (lane == 0) g_xsq[w] = s;
}

// ---------------- k_argmin: fused distance GEMM + argmin ----------------
__global__ void __launch_bounds__(256, 2)
k_argmin(const float* __restrict__ x, const float* __restrict__ e, int N, int K) {
    __shared__ float Xs[TM * DC];
    __shared__ float Es[TN * DC];
    __shared__ unsigned long long best[TM];

    int tid = threadIdx.x;
    int tx = tid & 15, ty = tid >> 4;
    int m0 = blockIdx.x * TM;

    if (tid < TM) best[tid] = 0xFFFFFFFFFFFFFFFFULL;

    float xq[8];
    unsigned long long tbest[8];
#pragma unroll
    for (int mi = 0; mi < 8; mi++) {
        int m = (mi < 4) ? (4 * ty + mi) : (64 + 4 * ty + (mi - 4));
        xq[mi] = g_xsq[m0 + m];
        tbest[mi] = 0xFFFFFFFFFFFFFFFFULL;
    }

    float4* Xs4 = reinterpret_cast<float4*>(Xs);
    float4* Es4 = reinterpret_cast<float4*>(Es);

#pragma unroll 1
    for (int kt = 0; kt < K / TN; kt++) {
        int n0 = kt * TN;
        unsigned long long acc[8][4];
#pragma unroll
        for (int mi = 0; mi < 8; mi++)
#pragma unroll
            for (int p = 0; p < 4; p++) acc[mi][p] = 0ULL;

#pragma unroll 1
        for (int dc = 0; dc < D / DC; dc++) {
            __syncthreads();
            load_tile(Xs4, x + (size_t)m0 * D + dc * DC, tid);
            load_tile(Es4, e + (size_t)n0 * D + dc * DC, tid);
            __syncthreads();
            chunk_mma(Xs4, Es4, ty, tx, acc);
        }

        // epilogue: dist = (xsq + esq) - 2*dot   (matches reference op shape)
#pragma unroll
        for (int mi = 0; mi < 8; mi++) {
#pragma unroll
            for (int p = 0; p < 4; p++) {
                float2 v = up2(acc[mi][p]);
                int nb = (p < 2) ? (4 * tx + 2 * p) : (64 + 4 * tx + 2 * (p - 2));
                int gk0 = n0 + nb;
                float d0 = __fsub_rn(__fadd_rn(xq[mi], g_esq[gk0]),     2.0f * v.x);
                float d1 = __fsub_rn(__fadd_rn(xq[mi], g_esq[gk0 + 1]), 2.0f * v.y);
                unsigned long long c0 = ((unsigned long long)__float_as_uint(d0) << 32) | (unsigned)gk0;
                unsigned long long c1 = ((unsigned long long)__float_as_uint(d1) << 32) | (unsigned)(gk0 + 1);
                if (c0 < tbest[mi]) tbest[mi] = c0;
                if (c1 < tbest[mi]) tbest[mi] = c1;
            }
        }
    }

#pragma unroll
    for (int mi = 0; mi < 8; mi++) {
        int m = (mi < 4) ? (4 * ty + mi) : (64 + 4 * ty + (mi - 4));
        atomicMin(&best[m], tbest[mi]);
    }
    __syncthreads();
    if (tid < TM) g_idx[m0 + tid] = (int)(best[tid] & 0xFFFFFFFFu);
}

// ---------------- k_gather: quantized_st output, MSE, counts, idx output ----------------
__global__ void __launch_bounds__(256)
k_gather(const float* __restrict__ x, const float* __restrict__ e,
         float* __restrict__ outq, float* __restrict__ outidx, int N) {
    __shared__ float red[256];
    int tid = threadIdx.x;
    int t   = blockIdx.x * 16 + (tid >> 4);
    int seg = tid & 15;
    int k = g_idx[t];
    const float4* er = reinterpret_cast<const float4*>(e + (size_t)k * D);
    const float4* xr = reinterpret_cast<const float4*>(x + (size_t)t * D);
    float4* qr = reinterpret_cast<float4*>(outq + (size_t)t * D);
    float s = 0.f;
#pragma unroll
    for (int j = 0; j < 4; j++) {
        int c = seg + j * 16;                 // coalesced across the 16-thread group
        float4 q = er[c], xv = xr[c];
        qr[c] = q;
        float dx = q.x - xv.x, dy = q.y - xv.y, dz = q.z - xv.z, dw = q.w - xv.w;
        s += (dx * dx + dy * dy) + (dz * dz + dw * dw);
    }
    red[tid] = s; __syncthreads();
    for (int st = 128; st > 0; st >>= 1) { if (tid < st) red[tid] += red[tid + st]; __syncthreads(); }
    if (tid == 0) atomicAdd(&g_acc[0], red[0]);
    if (seg == 0) {
        outidx[t] = (float)k;
        atomicAdd(&g_counts[k], 1.0f);
    }
}

// ---------------- k_sim: sum |off-diagonal cosine similarity| ----------------
__global__ void __launch_bounds__(256, 2)
k_sim(const float* __restrict__ e, int K) {
    __shared__ float As[TM * DC];
    __shared__ float Bs[TN * DC];
    __shared__ float red[256];

    int tid = threadIdx.x;
    int tx = tid & 15, ty = tid >> 4;
    int m0 = blockIdx.y * TM;
    int n0 = blockIdx.x * TN;

    float4* As4 = reinterpret_cast<float4*>(As);
    float4* Bs4 = reinterpret_cast<float4*>(Bs);

    unsigned long long acc[8][4];
#pragma unroll
    for (int mi = 0; mi < 8; mi++)
#pragma unroll
        for (int p = 0; p < 4; p++) acc[mi][p] = 0ULL;

#pragma unroll 1
    for (int dc = 0; dc < D / DC; dc++) {
        __syncthreads();
        load_tile(As4, e + (size_t)m0 * D + dc * DC, tid);
        load_tile(Bs4, e + (size_t)n0 * D + dc * DC, tid);
        __syncthreads();
        chunk_mma(As4, Bs4, ty, tx, acc);
    }

    float s = 0.f;
#pragma unroll
    for (int mi = 0; mi < 8; mi++) {
        int m = (mi < 4) ? (4 * ty + mi) : (64 + 4 * ty + (mi - 4));
        int gm = m0 + m;
        float rim = g_rninv[gm];
#pragma unroll
        for (int p = 0; p < 4; p++) {
            float2 v = up2(acc[mi][p]);
            int nb = (p < 2) ? (4 * tx + 2 * p) : (64 + 4 * tx + 2 * (p - 2));
            int gn0 = n0 + nb;
            float s0 = fabsf(v.x * rim * g_rninv[gn0]);
            float s1 = fabsf(v.y * rim * g_rninv[gn0 + 1]);
            if (gm == gn0)     s0 = 0.f;
            if (gm == gn0 + 1) s1 = 0.f;
            s += s0 + s1;
        }
    }
    red[tid] = s; __syncthreads();
    for (int st = 128; st > 0; st >>= 1) { if (tid < st) red[tid] += red[tid + st]; __syncthreads(); }
    if (tid == 0) atomicAdd(&g_acc[1], red[0]);
}

// ---------------- k_final: KL, perplexity, losses, scalar outputs ----------------
__global__ void k_final(float* __restrict__ out_loss, float* __restrict__ out_perp, int N, int K) {
    __shared__ float sA[256], sB[256], sC[256];
    int tid = threadIdx.x;

    float tot = 0.f;
    for (int k = tid; k < K; k += 256) tot += g_counts[k];
    sA[tid] = tot; __syncthreads();
    for (int st = 128; st > 0; st >>= 1) { if (tid < st) sA[tid] += sA[tid + st]; __syncthreads(); }
    float total = sA[0];
    __syncthreads();

    float tuni = 1.0f / (float)K;
    float kl = 0.f, pl = 0.f;
    for (int k = tid; k < K; k += 256) {
        float p = g_counts[k] / total;
        kl += (p + EPS_F) * logf((p + EPS_F) / (tuni + EPS_F));
        if (p > 0.f) pl += p * logf(p);
    }
    sB[tid] = kl; sC[tid] = pl; __syncthreads();
    for (int st = 128; st > 0; st >>= 1) {
        if (tid < st) { sB[tid] += sB[tid + st]; sC[tid] += sC[tid + st]; }
        __syncthreads();
    }
    if (tid == 0) {
        float klv = fminf(sB[0], 100.0f);
        float mse = g_acc[0] / ((float)N * (float)D);
        float vq  = mse + COMMIT_COST * mse;           // q_latent + 0.25*e_latent
        float l2  = fminf(g_acc[2] / (float)K, 10.0f);
        float orth = fminf(g_acc[1] / ((float)K * (float)K), 10.0f);
        float reg = l2 + orth;
        float loss = fminf(vq + DIV_GAMMA * klv + 0.01f * reg, 100.0f);
        *out_loss = loss;
        *out_perp = expf(-sC[0]);
    }
}

// ---------------- launch ----------------
extern "C" void kernel_launch(void* const* d_in, const int* in_sizes, int n_in,
                              void* d_out, int out_size) {
    const float* x = (const float*)d_in[0];
    const float* e = (const float*)d_in[1];
    float* out = (float*)d_out;

    int N = in_sizes[0] / D;   // 65536
    int K = in_sizes[1] / D;   // 2048
    if (N > MAXN) N = MAXN;
    if (K > MAXK) K = MAXK;

    float* out_q    = out;                       // [N, D] quantized_st
    float* out_loss = out + (size_t)N * D;       // scalar total_loss
    float* out_perp = out_loss + 1;              // scalar perplexity
    float* out_idx  = out_perp + 1;              // [N] indices (as float)

    k_init  <<<(K + 255) / 256, 256>>>(K);
    k_prep  <<<(K + 7) / 8, 256>>>(e, K);
    k_xsq   <<<(N + 7) / 8, 256>>>(x, N);
    k_argmin<<<N / TM, 256>>>(x, e, N, K);
    k_gather<<<N / 16, 256>>>(x, e, out_q, out_idx, N);
    k_sim   <<<dim3(K / TN, K / TM), 256>>>(e, K);
    k_final <<<1, 256>>>(out_loss, out_perp, N, K);
}